// round 15
// baseline (speedup 1.0000x reference)
#include <cuda_runtime.h>
#include <cuda_bf16.h>
#include <math.h>

// Coarse entry: [s:13][d:13][key:26]; fine entry: [fbl:6][lslot:14][key:26]
//   key = ((i+1)<<3)|clamped  -> max(key) == last-write-wins (JAX scatter order)
#define KEY_MASK 0x3FFFFFFull
#define D_SHIFT 26
#define S_SHIFT 39
#define F_SHIFT 26

#define CSH 7                          // 128 rows per coarse bucket
#define NC_MAX 48
#define CAP_C 196608
#define NFPC 64                        // fine buckets per coarse (128 rows / 2)
#define NBF_MAX (NC_MAX * NFPC)        // 3072
#define CAP_F 4096

#define CB_TPB 512
#define CB_VPT 4
#define CB_PER (CB_TPB * CB_VPT)       // 2048 pairs / coarse-bin CTA
#define FB_TPB 512
#define FB_VPT 4
#define FB_PER (FB_TPB * FB_VPT)       // 2048 entries / fine-bin CTA
#define BPB_F (CAP_C / FB_PER)         // 96 fine-bin CTAs per coarse bucket
#define TILE_TPB 512

__device__ __align__(16) unsigned long long g_cbins[(size_t)NC_MAX * CAP_C];
__device__ __align__(16) unsigned long long g_fbins[(size_t)NBF_MAX * CAP_F];
__device__ int g_ccur[NC_MAX];         // zero-init at load; re-zeroed by tile pass
__device__ int g_fcur[NBF_MAX];        // zero-init at load; re-zeroed by tile pass

// warp 0 computes exclusive prefix of s_cnt[0..nb) (nb <= 64) into s_start
__device__ __forceinline__ void warp_scan64(const int* s_cnt, int* s_start, int nb,
                                            int tid) {
    if (tid < 32) {
        int v = (tid < nb) ? s_cnt[tid] : 0;
        int orig = v;
#pragma unroll
        for (int off = 1; off < 32; off <<= 1) {
            int t = __shfl_up_sync(0xffffffffu, v, off);
            if (tid >= off) v += t;
        }
        if (tid < nb) s_start[tid] = v - orig;
        int total0 = __shfl_sync(0xffffffffu, v, 31);
        int i2 = tid + 32;
        if (nb > 32) {
            int v2 = (i2 < nb) ? s_cnt[i2] : 0;
            int orig2 = v2;
#pragma unroll
            for (int off = 1; off < 32; off <<= 1) {
                int t = __shfl_up_sync(0xffffffffu, v2, off);
                if (tid >= off) v2 += t;
            }
            if (i2 < nb) s_start[i2] = total0 + v2 - orig2;
        }
    }
}

__device__ __forceinline__ unsigned long long pack_coarse(int s, int d, int l,
                                                          int i, int maxpd) {
    unsigned key = ((unsigned)(i + 1) << 3) | (unsigned)(min(l, maxpd) - 1);
    return ((unsigned long long)s << S_SHIFT)
         | ((unsigned long long)d << D_SHIFT)
         | (unsigned long long)key;
}

// ---------- Pass 1: pairs -> 48 coarse buckets ----------
__global__ void __launch_bounds__(CB_TPB, 4)
coarse_bin_kernel(const int* __restrict__ src,
                  const int* __restrict__ dst,
                  const int* __restrict__ len,
                  int P, int maxpd, int nc) {
    __shared__ int s_cnt[NC_MAX];
    __shared__ int s_start[NC_MAX];
    __shared__ int s_goff[NC_MAX];
    extern __shared__ unsigned long long s_buf[];   // CB_PER * 8 = 16KB

    int tid = threadIdx.x;
    int base = blockIdx.x * CB_PER;
    if (tid < nc) s_cnt[tid] = 0;
    __syncthreads();

    unsigned long long e0, e1, e2, e3;
    int p0 = -1, p1 = -1, p2 = -1, p3 = -1;
    int i0 = base + tid * 4;                        // 4 consecutive pairs
    if (i0 + 4 <= P) {
        int4 s4 = *reinterpret_cast<const int4*>(src + i0);
        int4 d4 = *reinterpret_cast<const int4*>(dst + i0);
        int4 l4 = *reinterpret_cast<const int4*>(len + i0);
        e0 = pack_coarse(s4.x, d4.x, l4.x, i0 + 0, maxpd);
        e1 = pack_coarse(s4.y, d4.y, l4.y, i0 + 1, maxpd);
        e2 = pack_coarse(s4.z, d4.z, l4.z, i0 + 2, maxpd);
        e3 = pack_coarse(s4.w, d4.w, l4.w, i0 + 3, maxpd);
        p0 = atomicAdd(&s_cnt[s4.x >> CSH], 1);
        p1 = atomicAdd(&s_cnt[s4.y >> CSH], 1);
        p2 = atomicAdd(&s_cnt[s4.z >> CSH], 1);
        p3 = atomicAdd(&s_cnt[s4.w >> CSH], 1);
    } else {
        if (i0 + 0 < P) { e0 = pack_coarse(src[i0+0], dst[i0+0], len[i0+0], i0+0, maxpd);
                          p0 = atomicAdd(&s_cnt[src[i0+0] >> CSH], 1); }
        if (i0 + 1 < P) { e1 = pack_coarse(src[i0+1], dst[i0+1], len[i0+1], i0+1, maxpd);
                          p1 = atomicAdd(&s_cnt[src[i0+1] >> CSH], 1); }
        if (i0 + 2 < P) { e2 = pack_coarse(src[i0+2], dst[i0+2], len[i0+2], i0+2, maxpd);
                          p2 = atomicAdd(&s_cnt[src[i0+2] >> CSH], 1); }
        if (i0 + 3 < P) { e3 = pack_coarse(src[i0+3], dst[i0+3], len[i0+3], i0+3, maxpd);
                          p3 = atomicAdd(&s_cnt[src[i0+3] >> CSH], 1); }
    }
    __syncthreads();
    warp_scan64(s_cnt, s_start, nc, tid);
    __syncthreads();
    if (tid < nc) {
        int c = s_cnt[tid];
        int gb = (c > 0) ? atomicAdd(&g_ccur[tid], c) : 0;
        s_goff[tid] = gb - s_start[tid];
    }
    __syncthreads();
    if (p0 >= 0) s_buf[s_start[(int)(e0 >> (S_SHIFT + CSH))] + p0] = e0;
    if (p1 >= 0) s_buf[s_start[(int)(e1 >> (S_SHIFT + CSH))] + p1] = e1;
    if (p2 >= 0) s_buf[s_start[(int)(e2 >> (S_SHIFT + CSH))] + p2] = e2;
    if (p3 >= 0) s_buf[s_start[(int)(e3 >> (S_SHIFT + CSH))] + p3] = e3;
    __syncthreads();
    int tot = min(CB_PER, P - base);
    // vectorized copy-out: 2 consecutive entries per thread (LDS.128)
    for (int k = tid * 2; k < tot; k += CB_TPB * 2) {
        if (k + 1 < tot) {
            ulonglong2 vv = *reinterpret_cast<const ulonglong2*>(s_buf + k);
            int b0 = (int)(vv.x >> (S_SHIFT + CSH));
            int b1 = (int)(vv.y >> (S_SHIFT + CSH));
            int g0 = s_goff[b0] + k;
            int g1 = s_goff[b1] + k + 1;
            if ((unsigned)g0 < (unsigned)CAP_C)
                g_cbins[(size_t)b0 * CAP_C + g0] = vv.x;
            if ((unsigned)g1 < (unsigned)CAP_C)
                g_cbins[(size_t)b1 * CAP_C + g1] = vv.y;
        } else {
            unsigned long long ee = s_buf[k];
            int b = (int)(ee >> (S_SHIFT + CSH));
            int gpos = s_goff[b] + k;
            if ((unsigned)gpos < (unsigned)CAP_C)
                g_cbins[(size_t)b * CAP_C + gpos] = ee;
        }
    }
}

__device__ __forceinline__ unsigned long long pack_fine(unsigned long long v, int n) {
    int s = (int)(v >> S_SHIFT);
    int d = (int)(v >> D_SHIFT) & 0x1FFF;
    unsigned lslot = (unsigned)(s & 1) * (unsigned)n + (unsigned)d;
    int fbl = (s >> 1) & (NFPC - 1);
    return ((unsigned long long)fbl << 40)
         | ((unsigned long long)lslot << F_SHIFT)
         | (v & KEY_MASK);
}

// ---------- Pass 2: coarse -> fine buckets; emits (fbl<<40)|(lslot<<26)|key ----
__global__ void __launch_bounds__(FB_TPB, 4)
fine_bin_kernel(int n) {
    __shared__ int s_cnt[NFPC];
    __shared__ int s_start[NFPC];
    __shared__ int s_goff[NFPC];
    extern __shared__ unsigned long long s_buf[];   // FB_PER * 8 = 16KB

    int c = blockIdx.x / BPB_F;
    int blk = blockIdx.x % BPB_F;
    int count = min(g_ccur[c], (int)CAP_C);
    int base = blk * FB_PER;
    if (base >= count) return;
    int tot = min(FB_PER, count - base);
    const unsigned long long* cb = g_cbins + (size_t)c * CAP_C + base;

    int tid = threadIdx.x;
    if (tid < NFPC) s_cnt[tid] = 0;
    __syncthreads();

    unsigned long long e0, e1, e2, e3;
    int p0 = -1, p1 = -1, p2 = -1, p3 = -1;
    int k0 = tid * 2;                               // first ulonglong2
    int k1 = FB_TPB * 2 + tid * 2;                  // second ulonglong2
    if (k0 + 1 < tot) {
        ulonglong2 v = *reinterpret_cast<const ulonglong2*>(cb + k0);
        e0 = pack_fine(v.x, n); e1 = pack_fine(v.y, n);
        p0 = atomicAdd(&s_cnt[(int)(e0 >> 40)], 1);
        p1 = atomicAdd(&s_cnt[(int)(e1 >> 40)], 1);
    } else {
        if (k0 < tot) { e0 = pack_fine(cb[k0], n);
                        p0 = atomicAdd(&s_cnt[(int)(e0 >> 40)], 1); }
    }
    if (k1 + 1 < tot) {
        ulonglong2 v = *reinterpret_cast<const ulonglong2*>(cb + k1);
        e2 = pack_fine(v.x, n); e3 = pack_fine(v.y, n);
        p2 = atomicAdd(&s_cnt[(int)(e2 >> 40)], 1);
        p3 = atomicAdd(&s_cnt[(int)(e3 >> 40)], 1);
    } else {
        if (k1 < tot) { e2 = pack_fine(cb[k1], n);
                        p2 = atomicAdd(&s_cnt[(int)(e2 >> 40)], 1); }
    }
    __syncthreads();
    warp_scan64(s_cnt, s_start, NFPC, tid);
    __syncthreads();
    if (tid < NFPC) {
        int cnt = s_cnt[tid];
        int gb = (cnt > 0) ? atomicAdd(&g_fcur[c * NFPC + tid], cnt) : 0;
        s_goff[tid] = gb - s_start[tid];
    }
    __syncthreads();
    if (p0 >= 0) s_buf[s_start[(int)(e0 >> 40)] + p0] = e0;
    if (p1 >= 0) s_buf[s_start[(int)(e1 >> 40)] + p1] = e1;
    if (p2 >= 0) s_buf[s_start[(int)(e2 >> 40)] + p2] = e2;
    if (p3 >= 0) s_buf[s_start[(int)(e3 >> 40)] + p3] = e3;
    __syncthreads();
    int fb_base = c * NFPC;
    // vectorized copy-out: 2 consecutive entries per thread (LDS.128)
    for (int k = tid * 2; k < tot; k += FB_TPB * 2) {
        if (k + 1 < tot) {
            ulonglong2 vv = *reinterpret_cast<const ulonglong2*>(s_buf + k);
            int f0 = (int)(vv.x >> 40);
            int f1 = (int)(vv.y >> 40);
            int g0 = s_goff[f0] + k;
            int g1 = s_goff[f1] + k + 1;
            if ((unsigned)g0 < (unsigned)CAP_F)
                g_fbins[(size_t)(fb_base + f0) * CAP_F + g0] = vv.x & 0xFFFFFFFFFFull;
            if ((unsigned)g1 < (unsigned)CAP_F)
                g_fbins[(size_t)(fb_base + f1) * CAP_F + g1] = vv.y & 0xFFFFFFFFFFull;
        } else {
            unsigned long long ee = s_buf[k];
            int fbl = (int)(ee >> 40);
            int gpos = s_goff[fbl] + k;
            if ((unsigned)gpos < (unsigned)CAP_F)
                g_fbins[(size_t)(fb_base + fbl) * CAP_F + gpos] = ee & 0xFFFFFFFFFFull;
        }
    }
}

// ---------- Pass 3: fine bucket -> 2-row smem tile -> single output write ----
// Direct smem atomicMax scatter (ATOMS spread-addr ~2cyc/lane on B300 — cheaper
// than the race+repair STS/LDS dance). Also resets cursors for next replay.
__global__ void tile_kernel(float* __restrict__ out, const float* __restrict__ bvals,
                            int n, int maxpd, int nc) {
    extern __shared__ int s_tile[];    // 2 * n ints = 48000B for n=6000
    __shared__ float s_bias[8];
    int tid = threadIdx.x;
    int bucket = blockIdx.x;
    int row0 = bucket * 2;
    int rows = min(2, n - row0);
    int tilesz = rows * n;

    if (tid < 8) s_bias[tid] = (tid < maxpd) ? bvals[tid] : 0.0f;
    {
        int4 z4 = make_int4(0, 0, 0, 0);
        int t4 = tilesz >> 2;
        for (int i = tid; i < t4; i += TILE_TPB)
            reinterpret_cast<int4*>(s_tile)[i] = z4;
        for (int i = (t4 << 2) + tid; i < tilesz; i += TILE_TPB) s_tile[i] = 0;
    }
    __syncthreads();

    int cnt = min(g_fcur[bucket], (int)CAP_F);
    const unsigned long long* bin = g_fbins + (size_t)bucket * CAP_F;

    // fused scatter: vector load 2 entries, direct atomicMax each
    for (int k = tid * 2; k < cnt; k += TILE_TPB * 2) {
        if (k + 1 < cnt) {
            ulonglong2 v = *reinterpret_cast<const ulonglong2*>(bin + k);
            atomicMax(&s_tile[(int)(v.x >> F_SHIFT)], (int)(v.x & KEY_MASK));
            atomicMax(&s_tile[(int)(v.y >> F_SHIFT)], (int)(v.y & KEY_MASK));
        } else {
            unsigned long long v = bin[k];
            atomicMax(&s_tile[(int)(v >> F_SHIFT)], (int)(v & KEY_MASK));
        }
    }
    __syncthreads();

    float* orow = out + (size_t)row0 * n;
    int tot4 = tilesz >> 2;
    for (int q = tid; q < tot4; q += TILE_TPB) {
        int4 k4 = reinterpret_cast<const int4*>(s_tile)[q];
        float4 f;
        f.x = k4.x ? s_bias[k4.x & 7] : 0.0f;
        f.y = k4.y ? s_bias[k4.y & 7] : 0.0f;
        f.z = k4.z ? s_bias[k4.z & 7] : 0.0f;
        f.w = k4.w ? s_bias[k4.w & 7] : 0.0f;
        reinterpret_cast<float4*>(orow)[q] = f;
    }
    for (int q = tot4 * 4 + tid; q < tilesz; q += TILE_TPB) {
        int k = s_tile[q];
        orow[q] = k ? s_bias[k & 7] : 0.0f;
    }

    // cursor reset for the next replay (this CTA is the only reader of its slot)
    if (tid == 0) g_fcur[bucket] = 0;
    if (bucket == 0 && tid < nc) g_ccur[tid] = 0;
}

extern "C" void kernel_launch(void* const* d_in, const int* in_sizes, int n_in,
                              void* d_out, int out_size) {
    const float* b   = (const float*)d_in[1];
    const int*   src = (const int*)d_in[2];
    const int*   dst = (const int*)d_in[3];
    const int*   len = (const int*)d_in[4];
    float* out = (float*)d_out;

    long long total = (long long)out_size;
    int n = (int)llround(sqrt((double)total));
    int P = in_sizes[2];
    int maxpd = in_sizes[1];
    int nc = (n + (1 << CSH) - 1) >> CSH;
    int nbf = (n + 1) / 2;

    {
        int blocks = (P + CB_PER - 1) / CB_PER;
        size_t shmem = (size_t)CB_PER * sizeof(unsigned long long);  // 16KB
        coarse_bin_kernel<<<blocks, CB_TPB, shmem>>>(src, dst, len, P, maxpd, nc);
    }

    {
        size_t shmem = (size_t)FB_PER * sizeof(unsigned long long);  // 16KB
        fine_bin_kernel<<<nc * BPB_F, FB_TPB, shmem>>>(n);
    }

    {
        size_t shmem = (size_t)2 * n * sizeof(int);   // 48000B <= 48KB default
        tile_kernel<<<nbf, TILE_TPB, shmem>>>(out, b, n, maxpd, nc);
    }
}

// round 16
// speedup vs baseline: 1.0750x; 1.0750x over previous
#include <cuda_runtime.h>
#include <cuda_bf16.h>
#include <math.h>

// Coarse entry: [s:13][d:13][key:26]; fine entry: [fbl:6][lslot:14][key:26]
//   key = ((i+1)<<3)|clamped  -> max(key) == last-write-wins (JAX scatter order)
#define KEY_MASK 0x3FFFFFFull
#define D_SHIFT 26
#define S_SHIFT 39
#define F_SHIFT 26

#define CSH 7                          // 128 rows per coarse bucket
#define NC_MAX 48
#define CAP_C 196608
#define NFPC 64                        // fine buckets per coarse (128 rows / 2)
#define NBF_MAX (NC_MAX * NFPC)        // 3072
#define CAP_F 4096

#define CB_TPB 512
#define CB_VPT 4
#define CB_PER (CB_TPB * CB_VPT)       // 2048 pairs / coarse-bin CTA
#define FB_TPB 512
#define FB_VPT 4
#define FB_PER (FB_TPB * FB_VPT)       // 2048 entries / fine-bin CTA
#define BPB_F (CAP_C / FB_PER)         // 96 fine-bin CTAs per coarse bucket
#define TILE_TPB 512

__device__ __align__(16) unsigned long long g_cbins[(size_t)NC_MAX * CAP_C];
__device__ __align__(16) unsigned long long g_fbins[(size_t)NBF_MAX * CAP_F];
__device__ int g_ccur[NC_MAX];         // zero-init at load; re-zeroed by tile pass
__device__ int g_fcur[NBF_MAX];        // zero-init at load; re-zeroed by tile pass

// warp 0 computes exclusive prefix of s_cnt[0..nb) (nb <= 64) into s_start
__device__ __forceinline__ void warp_scan64(const int* s_cnt, int* s_start, int nb,
                                            int tid) {
    if (tid < 32) {
        int v = (tid < nb) ? s_cnt[tid] : 0;
        int orig = v;
#pragma unroll
        for (int off = 1; off < 32; off <<= 1) {
            int t = __shfl_up_sync(0xffffffffu, v, off);
            if (tid >= off) v += t;
        }
        if (tid < nb) s_start[tid] = v - orig;
        int total0 = __shfl_sync(0xffffffffu, v, 31);
        int i2 = tid + 32;
        if (nb > 32) {
            int v2 = (i2 < nb) ? s_cnt[i2] : 0;
            int orig2 = v2;
#pragma unroll
            for (int off = 1; off < 32; off <<= 1) {
                int t = __shfl_up_sync(0xffffffffu, v2, off);
                if (tid >= off) v2 += t;
            }
            if (i2 < nb) s_start[i2] = total0 + v2 - orig2;
        }
    }
}

__device__ __forceinline__ unsigned long long pack_coarse(int s, int d, int l,
                                                          int i, int maxpd) {
    unsigned key = ((unsigned)(i + 1) << 3) | (unsigned)(min(l, maxpd) - 1);
    return ((unsigned long long)s << S_SHIFT)
         | ((unsigned long long)d << D_SHIFT)
         | (unsigned long long)key;
}

// ---------- Pass 1: pairs -> 48 coarse buckets ----------
__global__ void __launch_bounds__(CB_TPB, 4)
coarse_bin_kernel(const int* __restrict__ src,
                  const int* __restrict__ dst,
                  const int* __restrict__ len,
                  int P, int maxpd, int nc) {
    __shared__ int s_cnt[NC_MAX];
    __shared__ int s_start[NC_MAX];
    __shared__ int s_goff[NC_MAX];
    extern __shared__ unsigned long long s_buf[];   // CB_PER * 8 = 16KB

    int tid = threadIdx.x;
    int base = blockIdx.x * CB_PER;
    if (tid < nc) s_cnt[tid] = 0;
    __syncthreads();

    unsigned long long e0, e1, e2, e3;
    int p0 = -1, p1 = -1, p2 = -1, p3 = -1;
    int i0 = base + tid * 4;                        // 4 consecutive pairs
    if (i0 + 4 <= P) {
        int4 s4 = *reinterpret_cast<const int4*>(src + i0);
        int4 d4 = *reinterpret_cast<const int4*>(dst + i0);
        int4 l4 = *reinterpret_cast<const int4*>(len + i0);
        e0 = pack_coarse(s4.x, d4.x, l4.x, i0 + 0, maxpd);
        e1 = pack_coarse(s4.y, d4.y, l4.y, i0 + 1, maxpd);
        e2 = pack_coarse(s4.z, d4.z, l4.z, i0 + 2, maxpd);
        e3 = pack_coarse(s4.w, d4.w, l4.w, i0 + 3, maxpd);
        p0 = atomicAdd(&s_cnt[s4.x >> CSH], 1);
        p1 = atomicAdd(&s_cnt[s4.y >> CSH], 1);
        p2 = atomicAdd(&s_cnt[s4.z >> CSH], 1);
        p3 = atomicAdd(&s_cnt[s4.w >> CSH], 1);
    } else {
        if (i0 + 0 < P) { e0 = pack_coarse(src[i0+0], dst[i0+0], len[i0+0], i0+0, maxpd);
                          p0 = atomicAdd(&s_cnt[src[i0+0] >> CSH], 1); }
        if (i0 + 1 < P) { e1 = pack_coarse(src[i0+1], dst[i0+1], len[i0+1], i0+1, maxpd);
                          p1 = atomicAdd(&s_cnt[src[i0+1] >> CSH], 1); }
        if (i0 + 2 < P) { e2 = pack_coarse(src[i0+2], dst[i0+2], len[i0+2], i0+2, maxpd);
                          p2 = atomicAdd(&s_cnt[src[i0+2] >> CSH], 1); }
        if (i0 + 3 < P) { e3 = pack_coarse(src[i0+3], dst[i0+3], len[i0+3], i0+3, maxpd);
                          p3 = atomicAdd(&s_cnt[src[i0+3] >> CSH], 1); }
    }
    __syncthreads();
    warp_scan64(s_cnt, s_start, nc, tid);
    __syncthreads();
    if (tid < nc) {
        int c = s_cnt[tid];
        int gb = (c > 0) ? atomicAdd(&g_ccur[tid], c) : 0;
        s_goff[tid] = gb - s_start[tid];
    }
    __syncthreads();
    if (p0 >= 0) s_buf[s_start[(int)(e0 >> (S_SHIFT + CSH))] + p0] = e0;
    if (p1 >= 0) s_buf[s_start[(int)(e1 >> (S_SHIFT + CSH))] + p1] = e1;
    if (p2 >= 0) s_buf[s_start[(int)(e2 >> (S_SHIFT + CSH))] + p2] = e2;
    if (p3 >= 0) s_buf[s_start[(int)(e3 >> (S_SHIFT + CSH))] + p3] = e3;
    __syncthreads();
    int tot = min(CB_PER, P - base);
    // lane-adjacent copy-out (coalesced within bucket segment runs)
    for (int k = tid; k < tot; k += CB_TPB) {
        unsigned long long ee = s_buf[k];
        int b = (int)(ee >> (S_SHIFT + CSH));
        int gpos = s_goff[b] + k;
        if ((unsigned)gpos < (unsigned)CAP_C)
            g_cbins[(size_t)b * CAP_C + gpos] = ee;
    }
}

__device__ __forceinline__ unsigned long long pack_fine(unsigned long long v, int n) {
    int s = (int)(v >> S_SHIFT);
    int d = (int)(v >> D_SHIFT) & 0x1FFF;
    unsigned lslot = (unsigned)(s & 1) * (unsigned)n + (unsigned)d;
    int fbl = (s >> 1) & (NFPC - 1);
    return ((unsigned long long)fbl << 40)
         | ((unsigned long long)lslot << F_SHIFT)
         | (v & KEY_MASK);
}

// ---------- Pass 2: coarse -> fine buckets; emits (fbl<<40)|(lslot<<26)|key ----
__global__ void __launch_bounds__(FB_TPB, 4)
fine_bin_kernel(int n) {
    __shared__ int s_cnt[NFPC];
    __shared__ int s_start[NFPC];
    __shared__ int s_goff[NFPC];
    extern __shared__ unsigned long long s_buf[];   // FB_PER * 8 = 16KB

    int c = blockIdx.x / BPB_F;
    int blk = blockIdx.x % BPB_F;
    int count = min(g_ccur[c], (int)CAP_C);
    int base = blk * FB_PER;
    if (base >= count) return;
    int tot = min(FB_PER, count - base);
    const unsigned long long* cb = g_cbins + (size_t)c * CAP_C + base;

    int tid = threadIdx.x;
    if (tid < NFPC) s_cnt[tid] = 0;
    __syncthreads();

    unsigned long long e0, e1, e2, e3;
    int p0 = -1, p1 = -1, p2 = -1, p3 = -1;
    int k0 = tid * 2;                               // first ulonglong2
    int k1 = FB_TPB * 2 + tid * 2;                  // second ulonglong2
    if (k0 + 1 < tot) {
        ulonglong2 v = *reinterpret_cast<const ulonglong2*>(cb + k0);
        e0 = pack_fine(v.x, n); e1 = pack_fine(v.y, n);
        p0 = atomicAdd(&s_cnt[(int)(e0 >> 40)], 1);
        p1 = atomicAdd(&s_cnt[(int)(e1 >> 40)], 1);
    } else {
        if (k0 < tot) { e0 = pack_fine(cb[k0], n);
                        p0 = atomicAdd(&s_cnt[(int)(e0 >> 40)], 1); }
    }
    if (k1 + 1 < tot) {
        ulonglong2 v = *reinterpret_cast<const ulonglong2*>(cb + k1);
        e2 = pack_fine(v.x, n); e3 = pack_fine(v.y, n);
        p2 = atomicAdd(&s_cnt[(int)(e2 >> 40)], 1);
        p3 = atomicAdd(&s_cnt[(int)(e3 >> 40)], 1);
    } else {
        if (k1 < tot) { e2 = pack_fine(cb[k1], n);
                        p2 = atomicAdd(&s_cnt[(int)(e2 >> 40)], 1); }
    }
    __syncthreads();
    warp_scan64(s_cnt, s_start, NFPC, tid);
    __syncthreads();
    if (tid < NFPC) {
        int cnt = s_cnt[tid];
        int gb = (cnt > 0) ? atomicAdd(&g_fcur[c * NFPC + tid], cnt) : 0;
        s_goff[tid] = gb - s_start[tid];
    }
    __syncthreads();
    if (p0 >= 0) s_buf[s_start[(int)(e0 >> 40)] + p0] = e0;
    if (p1 >= 0) s_buf[s_start[(int)(e1 >> 40)] + p1] = e1;
    if (p2 >= 0) s_buf[s_start[(int)(e2 >> 40)] + p2] = e2;
    if (p3 >= 0) s_buf[s_start[(int)(e3 >> 40)] + p3] = e3;
    __syncthreads();
    int fb_base = c * NFPC;
    // lane-adjacent copy-out (coalesced within bucket segment runs)
    for (int k = tid; k < tot; k += FB_TPB) {
        unsigned long long ee = s_buf[k];
        int fbl = (int)(ee >> 40);
        int gpos = s_goff[fbl] + k;
        if ((unsigned)gpos < (unsigned)CAP_F)
            g_fbins[(size_t)(fb_base + fbl) * CAP_F + gpos] = ee & 0xFFFFFFFFFFull;
    }
}

// ---------- Pass 3: fine bucket -> 2-row smem tile -> single output write ----
// Direct smem atomicMax scatter (ATOMS spread-addr ~2cyc/lane on B300).
// Also resets cursors for the next graph replay.
__global__ void tile_kernel(float* __restrict__ out, const float* __restrict__ bvals,
                            int n, int maxpd, int nc) {
    extern __shared__ int s_tile[];    // 2 * n ints = 48000B for n=6000
    __shared__ float s_bias[8];
    int tid = threadIdx.x;
    int bucket = blockIdx.x;
    int row0 = bucket * 2;
    int rows = min(2, n - row0);
    int tilesz = rows * n;

    if (tid < 8) s_bias[tid] = (tid < maxpd) ? bvals[tid] : 0.0f;
    {
        int4 z4 = make_int4(0, 0, 0, 0);
        int t4 = tilesz >> 2;
        for (int i = tid; i < t4; i += TILE_TPB)
            reinterpret_cast<int4*>(s_tile)[i] = z4;
        for (int i = (t4 << 2) + tid; i < tilesz; i += TILE_TPB) s_tile[i] = 0;
    }
    __syncthreads();

    int cnt = min(g_fcur[bucket], (int)CAP_F);
    const unsigned long long* bin = g_fbins + (size_t)bucket * CAP_F;

    // fused scatter: vector load 2 entries, direct atomicMax each
    for (int k = tid * 2; k < cnt; k += TILE_TPB * 2) {
        if (k + 1 < cnt) {
            ulonglong2 v = *reinterpret_cast<const ulonglong2*>(bin + k);
            atomicMax(&s_tile[(int)(v.x >> F_SHIFT)], (int)(v.x & KEY_MASK));
            atomicMax(&s_tile[(int)(v.y >> F_SHIFT)], (int)(v.y & KEY_MASK));
        } else {
            unsigned long long v = bin[k];
            atomicMax(&s_tile[(int)(v >> F_SHIFT)], (int)(v & KEY_MASK));
        }
    }
    __syncthreads();

    float* orow = out + (size_t)row0 * n;
    int tot4 = tilesz >> 2;
    for (int q = tid; q < tot4; q += TILE_TPB) {
        int4 k4 = reinterpret_cast<const int4*>(s_tile)[q];
        float4 f;
        f.x = k4.x ? s_bias[k4.x & 7] : 0.0f;
        f.y = k4.y ? s_bias[k4.y & 7] : 0.0f;
        f.z = k4.z ? s_bias[k4.z & 7] : 0.0f;
        f.w = k4.w ? s_bias[k4.w & 7] : 0.0f;
        reinterpret_cast<float4*>(orow)[q] = f;
    }
    for (int q = tot4 * 4 + tid; q < tilesz; q += TILE_TPB) {
        int k = s_tile[q];
        orow[q] = k ? s_bias[k & 7] : 0.0f;
    }

    // cursor reset for the next replay (this CTA is the only reader of its slot)
    if (tid == 0) g_fcur[bucket] = 0;
    if (bucket == 0 && tid < nc) g_ccur[tid] = 0;
}

extern "C" void kernel_launch(void* const* d_in, const int* in_sizes, int n_in,
                              void* d_out, int out_size) {
    const float* b   = (const float*)d_in[1];
    const int*   src = (const int*)d_in[2];
    const int*   dst = (const int*)d_in[3];
    const int*   len = (const int*)d_in[4];
    float* out = (float*)d_out;

    long long total = (long long)out_size;
    int n = (int)llround(sqrt((double)total));
    int P = in_sizes[2];
    int maxpd = in_sizes[1];
    int nc = (n + (1 << CSH) - 1) >> CSH;
    int nbf = (n + 1) / 2;

    {
        int blocks = (P + CB_PER - 1) / CB_PER;
        size_t shmem = (size_t)CB_PER * sizeof(unsigned long long);  // 16KB
        coarse_bin_kernel<<<blocks, CB_TPB, shmem>>>(src, dst, len, P, maxpd, nc);
    }

    {
        size_t shmem = (size_t)FB_PER * sizeof(unsigned long long);  // 16KB
        fine_bin_kernel<<<nc * BPB_F, FB_TPB, shmem>>>(n);
    }

    {
        size_t shmem = (size_t)2 * n * sizeof(int);   // 48000B <= 48KB default
        tile_kernel<<<nbf, TILE_TPB, shmem>>>(out, b, n, maxpd, nc);
    }
}